// round 14
// baseline (speedup 1.0000x reference)
#include <cuda_runtime.h>
#include <stdint.h>
#include <math.h>

#define BATCH 32
#define SEQ   8400
#define NLAB  80
#define DIM   256
#define NQ    300
#define CAND  512
#define RPB   128     // rows per block in scores kernel (512 thr, 5 ld/thread)

// Scratch (allocation-free per harness rules)
__device__ unsigned int g_scores_u[BATCH * SEQ];

__device__ __forceinline__ unsigned int f32_sortable(float v) {
    unsigned int u = __float_as_uint(v);
    return (u & 0x80000000u) ? ~u : (u | 0x80000000u);
}
__device__ __forceinline__ void stg_cs_f4(float* p, float4 v) {
    asm volatile("st.global.cs.v4.f32 [%0], {%1,%2,%3,%4};"
                 :: "l"(p), "f"(v.x), "f"(v.y), "f"(v.z), "f"(v.w) : "memory");
}

// ---------------------------------------------------------------------------
// Kernel 1: scores (best measured: 512 thr, 5 float4/thread, smem transpose).
// ---------------------------------------------------------------------------
__global__ void __launch_bounds__(512) scores_kernel(const float* __restrict__ cls) {
    __shared__ float part[RPB * 20];

    const int t = threadIdx.x;
    const float4* base = (const float4*)cls + (size_t)blockIdx.x * (RPB * 20);
    #pragma unroll
    for (int i = 0; i < 5; ++i) {
        int idx = t + 512 * i;
        float4 v = __ldg(&base[idx]);
        part[idx] = fmaxf(fmaxf(v.x, v.y), fmaxf(v.z, v.w));
    }
    __syncthreads();
    {
        int row = t >> 2;
        int p   = t & 3;
        const float* q = &part[row * 20 + p * 5];
        float m = q[0];
        #pragma unroll
        for (int j = 1; j < 5; ++j) m = fmaxf(m, q[j]);
        m = fmaxf(m, __shfl_xor_sync(0xFFFFFFFFu, m, 1));
        m = fmaxf(m, __shfl_xor_sync(0xFFFFFFFFu, m, 2));
        if (p == 0)
            g_scores_u[blockIdx.x * RPB + row] = f32_sortable(m);
    }
}

// ---------------------------------------------------------------------------
// Kernel 2: per-batch top-300 (R8 register-resident version, known fast)
// PLUS in-block gather: sorted indices land in shared memory; after one
// barrier the same 32 warps gather all 300 queries of this batch directly.
// No third kernel, no handshake, no global index round-trip.
// Output layout (flattened tuple, return order):
//   [0]            init_reference_points (B,NQ,4)
//   [+B*NQ*4]      target                (B,NQ,256)
//   [+B*NQ*256]    enc_topk_logits       (B,NQ,80)
//   [+B*NQ*80]     enc_topk_bboxes       (B,NQ,4)
// ---------------------------------------------------------------------------
__global__ void __launch_bounds__(1024) topk_gather_kernel(
        const float* __restrict__ cls,
        const float* __restrict__ coord,
        const float* __restrict__ mem,
        float* __restrict__ out) {
    __shared__ unsigned int       s_wA[2][32];
    __shared__ unsigned int       s_wB[2][32];
    __shared__ unsigned int       s_woff[32];
    __shared__ unsigned int       s_cnt;
    __shared__ unsigned long long s_cand[CAND];
    __shared__ int                s_idx[NQ];      // sorted top-300 indices

    const int b    = blockIdx.x;
    const int tid  = threadIdx.x;
    const int lane = tid & 31;
    const int wid  = tid >> 5;
    const unsigned FULL = 0xFFFFFFFFu;

    const unsigned int* sc = g_scores_u + b * SEQ;

    uint4 va = ((const uint4*)sc)[tid];
    uint4 vb = ((const uint4*)sc)[tid + 1024];
    const bool hasTail = (tid < SEQ - 8192);           // 208
    unsigned int vt = hasTail ? sc[8192 + tid] : 0u;

    unsigned int vv[9];
    int si[9];
    vv[0]=va.x; vv[1]=va.y; vv[2]=va.z; vv[3]=va.w;
    vv[4]=vb.x; vv[5]=vb.y; vv[6]=vb.z; vv[7]=vb.w;
    vv[8]=hasTail ? vt : 0u;
    #pragma unroll
    for (int k = 0; k < 4; ++k) { si[k] = 4*tid + k; si[4+k] = 4096 + 4*tid + k; }
    si[8] = 8192 + tid;

    // ---- block max AND min ----
    unsigned int mx = 0, mn = 0xFFFFFFFFu;
    #pragma unroll
    for (int k = 0; k < 8; ++k) { mx = max(mx, vv[k]); mn = min(mn, vv[k]); }
    if (hasTail) { mx = max(mx, vv[8]); mn = min(mn, vv[8]); }
    #pragma unroll
    for (int o = 16; o > 0; o >>= 1) {
        mx = max(mx, __shfl_xor_sync(FULL, mx, o));
        mn = min(mn, __shfl_xor_sync(FULL, mn, o));
    }
    if (lane == 0) { s_wA[0][wid] = mx; s_wB[0][wid] = mn; }
    __syncthreads();
    unsigned int M = s_wA[0][lane];
    unsigned int m_lo = s_wB[0][lane];
    #pragma unroll
    for (int o = 16; o > 0; o >>= 1) {
        M    = max(M,    __shfl_xor_sync(FULL, M,    o));
        m_lo = min(m_lo, __shfl_xor_sync(FULL, m_lo, o));
    }

    // ---- quaternary search on 22-bit codes, 1 barrier/iteration ----
    unsigned int lo = m_lo >> 10, hi = (M >> 10) + 1;
    int parity = 1;
    while (hi - lo > 1) {
        unsigned int d  = hi - lo;
        unsigned int m1 = lo + (d >> 2); if (m1 == lo) m1 = lo + 1;
        unsigned int m2 = lo + (d >> 1); if (m2 == lo) m2 = lo + 1;
        unsigned int m3 = lo + d - (d >> 2); if (m3 >= hi) m3 = hi - 1;
        const unsigned int t1 = m1 << 10, t2 = m2 << 10, t3 = m3 << 10;

        unsigned int c12 = 0, c3 = 0;
        #pragma unroll
        for (int k = 0; k < 8; ++k) {
            unsigned int v = vv[k];
            c12 += (v >= t1) + ((v >= t2) << 16);
            c3  += (v >= t3);
        }
        if (hasTail) {
            unsigned int v = vv[8];
            c12 += (v >= t1) + ((v >= t2) << 16);
            c3  += (v >= t3);
        }
        #pragma unroll
        for (int o = 16; o > 0; o >>= 1) {
            c12 += __shfl_xor_sync(FULL, c12, o);
            c3  += __shfl_xor_sync(FULL, c3,  o);
        }
        if (lane == 0) { s_wA[parity][wid] = c12; s_wB[parity][wid] = c3; }
        __syncthreads();
        unsigned int a  = s_wA[parity][lane];
        unsigned int bb = s_wB[parity][lane];
        #pragma unroll
        for (int o = 16; o > 0; o >>= 1) {
            a  += __shfl_xor_sync(FULL, a,  o);
            bb += __shfl_xor_sync(FULL, bb, o);
        }
        const unsigned int cnt1 = a & 0xFFFFu;
        const unsigned int cnt2 = a >> 16;
        const unsigned int cnt3 = bb;

        if      (cnt3 >= NQ) lo = m3;
        else if (cnt2 >= NQ) { lo = m2; hi = m3; }
        else if (cnt1 >= NQ) { lo = m1; hi = m2; }
        else                 hi = m1;
        parity ^= 1;
    }
    const unsigned int T = lo << 10;

    // ---- compact candidates via block prefix scan ----
    bool hit[9];
    int myc = 0;
    #pragma unroll
    for (int k = 0; k < 8; ++k) { hit[k] = (vv[k] >= T); myc += hit[k]; }
    hit[8] = hasTail && (vv[8] >= T); myc += hit[8];

    int inc = myc;
    #pragma unroll
    for (int o = 1; o < 32; o <<= 1) {
        int t2 = __shfl_up_sync(FULL, inc, o);
        if (lane >= o) inc += t2;
    }
    __syncthreads();
    if (lane == 31) s_wA[0][wid] = (unsigned)inc;
    __syncthreads();
    if (tid < 32) {
        unsigned int v = s_wA[0][tid];
        unsigned int i2 = v;
        #pragma unroll
        for (int o = 1; o < 32; o <<= 1) {
            unsigned int t2 = __shfl_up_sync(FULL, i2, o);
            if (tid >= o) i2 += t2;
        }
        s_woff[tid] = i2 - v;
        if (tid == 31) s_cnt = i2;
    }
    __syncthreads();

    int pos = (int)s_woff[wid] + (inc - myc);
    #pragma unroll
    for (int k = 0; k < 9; ++k) {
        if (hit[k]) {
            if (pos < CAND)
                s_cand[pos] = ((unsigned long long)vv[k] << 32) |
                              (unsigned int)(SEQ - 1 - si[k]);
            ++pos;
        }
    }
    __syncthreads();

    // ---- sync-free ranking -> sorted indices into SHARED memory ----
    const int cntC = (int)min(s_cnt, (unsigned)CAND);
    if (tid < cntC) {
        const unsigned long long mine = s_cand[tid];
        int rank = 0;
        for (int j = 0; j < cntC; ++j)
            rank += (s_cand[j] > mine);
        if (rank < NQ)
            s_idx[rank] = SEQ - 1 - (int)(unsigned int)(mine & 0xFFFFFFFFull);
    }
    __syncthreads();

    // ================= in-block gather: 32 warps x ~9.4 queries =============
    float* out_tgt  = out + (size_t)BATCH * NQ * 4;
    float* out_log  = out_tgt + (size_t)BATCH * NQ * DIM;
    float* out_bbox = out_log + (size_t)BATCH * NQ * NLAB;

    for (int q = wid; q < NQ; q += 32) {
        const int bq = b * NQ + q;
        const int s  = s_idx[q];                        // LDS broadcast
        const size_t src = (size_t)b * SEQ + (size_t)s;

        float4 lg, cd;
        if (lane < 20)
            lg = __ldg(&((const float4*)(cls + src * NLAB))[lane]);
        if (lane == 20)
            cd = __ldg((const float4*)(coord + src * 4));
        const float4* m4 = (const float4*)(mem + src * DIM);
        float4 m0 = __ldg(&m4[lane]);
        float4 m1 = __ldg(&m4[lane + 32]);

        float* o = out_tgt + (size_t)bq * DIM;
        stg_cs_f4(o + 4 * lane,        m0);
        stg_cs_f4(o + 4 * (lane + 32), m1);
        if (lane < 20)
            stg_cs_f4(out_log + (size_t)bq * NLAB + 4 * lane, lg);
        if (lane == 20) {
            stg_cs_f4(out + (size_t)bq * 4, cd);
            float4 sg;
            sg.x = 1.0f / (1.0f + __expf(-cd.x));
            sg.y = 1.0f / (1.0f + __expf(-cd.y));
            sg.z = 1.0f / (1.0f + __expf(-cd.z));
            sg.w = 1.0f / (1.0f + __expf(-cd.w));
            stg_cs_f4(out_bbox + (size_t)bq * 4, sg);
        }
    }
}

// ---------------------------------------------------------------------------
extern "C" void kernel_launch(void* const* d_in, const int* in_sizes, int n_in,
                              void* d_out, int out_size) {
    const float* cls   = (const float*)d_in[0];  // (32, 8400, 80)
    const float* coord = (const float*)d_in[1];  // (32, 8400, 4)
    const float* mem   = (const float*)d_in[2];  // (32, 8400, 256)
    float* out = (float*)d_out;

    scores_kernel<<<(BATCH * SEQ) / RPB, 512>>>(cls);        // 2100 blocks
    topk_gather_kernel<<<BATCH, 1024>>>(cls, coord, mem, out);  // 32 blocks
}

// round 15
// speedup vs baseline: 1.3402x; 1.3402x over previous
#include <cuda_runtime.h>
#include <stdint.h>
#include <math.h>

#define BATCH 32
#define SEQ   8400
#define NLAB  80
#define DIM   256
#define NQ    300
#define CAND  512
#define RPB   128     // rows per block in scores kernel (512 thr, 5 ld/thread)

// Scratch (allocation-free per harness rules)
__device__ unsigned int g_scores_u[BATCH * SEQ];  // sortable-uint scores
__device__ int          g_topk[BATCH * NQ];

__device__ __forceinline__ unsigned int f32_sortable(float v) {
    unsigned int u = __float_as_uint(v);
    return (u & 0x80000000u) ? ~u : (u | 0x80000000u);
}
__device__ __forceinline__ void stg_cs_f4(float* p, float4 v) {
    asm volatile("st.global.cs.v4.f32 [%0], {%1,%2,%3,%4};"
                 :: "l"(p), "f"(v.x), "f"(v.y), "f"(v.z), "f"(v.w) : "memory");
}
__device__ __forceinline__ void pdl_wait() {
    asm volatile("griddepcontrol.wait;" ::: "memory");
}
__device__ __forceinline__ void pdl_launch_dependents() {
    asm volatile("griddepcontrol.launch_dependents;" ::: "memory");
}

// ---------------------------------------------------------------------------
// Kernel 1: scores (best measured: 512 thr, 5 float4/thread, smem transpose).
// Fires launch_dependents right after its final store.
// ---------------------------------------------------------------------------
__global__ void __launch_bounds__(512) scores_kernel(const float* __restrict__ cls) {
    __shared__ float part[RPB * 20];

    const int t = threadIdx.x;
    const float4* base = (const float4*)cls + (size_t)blockIdx.x * (RPB * 20);
    #pragma unroll
    for (int i = 0; i < 5; ++i) {
        int idx = t + 512 * i;
        float4 v = __ldg(&base[idx]);
        part[idx] = fmaxf(fmaxf(v.x, v.y), fmaxf(v.z, v.w));
    }
    __syncthreads();
    {
        int row = t >> 2;
        int p   = t & 3;
        const float* q = &part[row * 20 + p * 5];
        float m = q[0];
        #pragma unroll
        for (int j = 1; j < 5; ++j) m = fmaxf(m, q[j]);
        m = fmaxf(m, __shfl_xor_sync(0xFFFFFFFFu, m, 1));
        m = fmaxf(m, __shfl_xor_sync(0xFFFFFFFFu, m, 2));
        if (p == 0)
            g_scores_u[blockIdx.x * RPB + row] = f32_sortable(m);
    }
    pdl_launch_dependents();
}

// ---------------------------------------------------------------------------
// Kernel 2: per-batch exact top-300 (R8/R10 register-resident version).
// Opens with griddepcontrol.wait; fires launch_dependents after its stores.
// ---------------------------------------------------------------------------
__global__ void __launch_bounds__(1024) topk_kernel() {
    __shared__ unsigned int       s_wA[2][32];
    __shared__ unsigned int       s_wB[2][32];
    __shared__ unsigned int       s_woff[32];
    __shared__ unsigned int       s_cnt;
    __shared__ unsigned long long s_cand[CAND];

    pdl_wait();

    const int b    = blockIdx.x;
    const int tid  = threadIdx.x;
    const int lane = tid & 31;
    const int wid  = tid >> 5;
    const unsigned FULL = 0xFFFFFFFFu;

    const unsigned int* sc = g_scores_u + b * SEQ;

    uint4 va = ((const uint4*)sc)[tid];
    uint4 vb = ((const uint4*)sc)[tid + 1024];
    const bool hasTail = (tid < SEQ - 8192);           // 208
    unsigned int vt = hasTail ? sc[8192 + tid] : 0u;

    unsigned int vv[9];
    int si[9];
    vv[0]=va.x; vv[1]=va.y; vv[2]=va.z; vv[3]=va.w;
    vv[4]=vb.x; vv[5]=vb.y; vv[6]=vb.z; vv[7]=vb.w;
    vv[8]=hasTail ? vt : 0u;
    #pragma unroll
    for (int k = 0; k < 4; ++k) { si[k] = 4*tid + k; si[4+k] = 4096 + 4*tid + k; }
    si[8] = 8192 + tid;

    // ---- block max AND min ----
    unsigned int mx = 0, mn = 0xFFFFFFFFu;
    #pragma unroll
    for (int k = 0; k < 8; ++k) { mx = max(mx, vv[k]); mn = min(mn, vv[k]); }
    if (hasTail) { mx = max(mx, vv[8]); mn = min(mn, vv[8]); }
    #pragma unroll
    for (int o = 16; o > 0; o >>= 1) {
        mx = max(mx, __shfl_xor_sync(FULL, mx, o));
        mn = min(mn, __shfl_xor_sync(FULL, mn, o));
    }
    if (lane == 0) { s_wA[0][wid] = mx; s_wB[0][wid] = mn; }
    __syncthreads();
    unsigned int M = s_wA[0][lane];
    unsigned int m_lo = s_wB[0][lane];
    #pragma unroll
    for (int o = 16; o > 0; o >>= 1) {
        M    = max(M,    __shfl_xor_sync(FULL, M,    o));
        m_lo = min(m_lo, __shfl_xor_sync(FULL, m_lo, o));
    }

    // ---- quaternary search on 22-bit codes, 1 barrier/iteration ----
    unsigned int lo = m_lo >> 10, hi = (M >> 10) + 1;
    int parity = 1;
    while (hi - lo > 1) {
        unsigned int d  = hi - lo;
        unsigned int m1 = lo + (d >> 2); if (m1 == lo) m1 = lo + 1;
        unsigned int m2 = lo + (d >> 1); if (m2 == lo) m2 = lo + 1;
        unsigned int m3 = lo + d - (d >> 2); if (m3 >= hi) m3 = hi - 1;
        const unsigned int t1 = m1 << 10, t2 = m2 << 10, t3 = m3 << 10;

        unsigned int c12 = 0, c3 = 0;
        #pragma unroll
        for (int k = 0; k < 8; ++k) {
            unsigned int v = vv[k];
            c12 += (v >= t1) + ((v >= t2) << 16);
            c3  += (v >= t3);
        }
        if (hasTail) {
            unsigned int v = vv[8];
            c12 += (v >= t1) + ((v >= t2) << 16);
            c3  += (v >= t3);
        }
        #pragma unroll
        for (int o = 16; o > 0; o >>= 1) {
            c12 += __shfl_xor_sync(FULL, c12, o);
            c3  += __shfl_xor_sync(FULL, c3,  o);
        }
        if (lane == 0) { s_wA[parity][wid] = c12; s_wB[parity][wid] = c3; }
        __syncthreads();
        unsigned int a  = s_wA[parity][lane];
        unsigned int bb = s_wB[parity][lane];
        #pragma unroll
        for (int o = 16; o > 0; o >>= 1) {
            a  += __shfl_xor_sync(FULL, a,  o);
            bb += __shfl_xor_sync(FULL, bb, o);
        }
        const unsigned int cnt1 = a & 0xFFFFu;
        const unsigned int cnt2 = a >> 16;
        const unsigned int cnt3 = bb;

        if      (cnt3 >= NQ) lo = m3;
        else if (cnt2 >= NQ) { lo = m2; hi = m3; }
        else if (cnt1 >= NQ) { lo = m1; hi = m2; }
        else                 hi = m1;
        parity ^= 1;
    }
    const unsigned int T = lo << 10;

    // ---- compact candidates via block prefix scan ----
    bool hit[9];
    int myc = 0;
    #pragma unroll
    for (int k = 0; k < 8; ++k) { hit[k] = (vv[k] >= T); myc += hit[k]; }
    hit[8] = hasTail && (vv[8] >= T); myc += hit[8];

    int inc = myc;
    #pragma unroll
    for (int o = 1; o < 32; o <<= 1) {
        int t2 = __shfl_up_sync(FULL, inc, o);
        if (lane >= o) inc += t2;
    }
    __syncthreads();
    if (lane == 31) s_wA[0][wid] = (unsigned)inc;
    __syncthreads();
    if (tid < 32) {
        unsigned int v = s_wA[0][tid];
        unsigned int i2 = v;
        #pragma unroll
        for (int o = 1; o < 32; o <<= 1) {
            unsigned int t2 = __shfl_up_sync(FULL, i2, o);
            if (tid >= o) i2 += t2;
        }
        s_woff[tid] = i2 - v;
        if (tid == 31) s_cnt = i2;
    }
    __syncthreads();

    int pos = (int)s_woff[wid] + (inc - myc);
    #pragma unroll
    for (int k = 0; k < 9; ++k) {
        if (hit[k]) {
            if (pos < CAND)
                s_cand[pos] = ((unsigned long long)vv[k] << 32) |
                              (unsigned int)(SEQ - 1 - si[k]);
            ++pos;
        }
    }
    __syncthreads();

    // ---- sync-free ranking: rank = #{j: key_j > key_i} ----
    const int cntC = (int)min(s_cnt, (unsigned)CAND);
    if (tid < cntC) {
        const unsigned long long mine = s_cand[tid];
        int rank = 0;
        for (int j = 0; j < cntC; ++j)
            rank += (s_cand[j] > mine);
        if (rank < NQ)
            g_topk[b * NQ + rank] =
                SEQ - 1 - (int)(unsigned int)(mine & 0xFFFFFFFFull);
    }
    __syncthreads();
    pdl_launch_dependents();
}

// ---------------------------------------------------------------------------
// Kernel 3: gather (R10 version). Opens with griddepcontrol.wait.
// 1200 blocks x 256 threads; one warp per query; small loads first;
// .cs streaming stores for the big target rows.
// Output layout (flattened tuple, return order):
//   [0]            init_reference_points (B,NQ,4)
//   [+B*NQ*4]      target                (B,NQ,256)
//   [+B*NQ*256]    enc_topk_logits       (B,NQ,80)
//   [+B*NQ*80]     enc_topk_bboxes       (B,NQ,4)
// ---------------------------------------------------------------------------
__global__ void __launch_bounds__(256) gather_kernel(const float* __restrict__ cls,
                              const float* __restrict__ coord,
                              const float* __restrict__ mem,
                              float* __restrict__ out) {
    pdl_wait();

    const int lane = threadIdx.x & 31;
    const int wid  = threadIdx.x >> 5;
    const int bq   = blockIdx.x * 8 + wid;

    float* out_tgt  = out + (size_t)BATCH * NQ * 4;
    float* out_log  = out_tgt + (size_t)BATCH * NQ * DIM;
    float* out_bbox = out_log + (size_t)BATCH * NQ * NLAB;

    const int s = __ldg(&g_topk[bq]);                 // broadcast load
    const size_t src = (size_t)(bq / NQ) * SEQ + (size_t)s;

    float4 lg, cd;
    if (lane < 20)
        lg = __ldg(&((const float4*)(cls + src * NLAB))[lane]);
    if (lane == 20)
        cd = __ldg((const float4*)(coord + src * 4));
    const float4* m4 = (const float4*)(mem + src * DIM);
    float4 m0 = __ldg(&m4[lane]);
    float4 m1 = __ldg(&m4[lane + 32]);

    float* o = out_tgt + (size_t)bq * DIM;
    stg_cs_f4(o + 4 * lane,        m0);
    stg_cs_f4(o + 4 * (lane + 32), m1);
    if (lane < 20)
        stg_cs_f4(out_log + (size_t)bq * NLAB + 4 * lane, lg);
    if (lane == 20) {
        stg_cs_f4(out + (size_t)bq * 4, cd);
        float4 sg;
        sg.x = 1.0f / (1.0f + __expf(-cd.x));
        sg.y = 1.0f / (1.0f + __expf(-cd.y));
        sg.z = 1.0f / (1.0f + __expf(-cd.z));
        sg.w = 1.0f / (1.0f + __expf(-cd.w));
        stg_cs_f4(out_bbox + (size_t)bq * 4, sg);
    }
}

// ---------------------------------------------------------------------------
extern "C" void kernel_launch(void* const* d_in, const int* in_sizes, int n_in,
                              void* d_out, int out_size) {
    const float* cls   = (const float*)d_in[0];  // (32, 8400, 80)
    const float* coord = (const float*)d_in[1];  // (32, 8400, 4)
    const float* mem   = (const float*)d_in[2];  // (32, 8400, 256)
    float* out = (float*)d_out;

    // Kernel 1: plain launch
    scores_kernel<<<(BATCH * SEQ) / RPB, 512>>>(cls);      // 2100 blocks

    // Kernels 2 & 3: PDL launches (prologue overlaps producer epilogue)
    cudaLaunchAttribute attr[1];
    attr[0].id = cudaLaunchAttributeProgrammaticStreamSerialization;
    attr[0].val.programmaticStreamSerializationAllowed = 1;

    {
        cudaLaunchConfig_t cfg = {};
        cfg.gridDim  = dim3(BATCH, 1, 1);
        cfg.blockDim = dim3(1024, 1, 1);
        cfg.dynamicSmemBytes = 0;
        cfg.stream = 0;
        cfg.attrs = attr;
        cfg.numAttrs = 1;
        cudaLaunchKernelEx(&cfg, topk_kernel);
    }
    {
        cudaLaunchConfig_t cfg = {};
        cfg.gridDim  = dim3((BATCH * NQ) / 8, 1, 1);       // 1200 blocks
        cfg.blockDim = dim3(256, 1, 1);
        cfg.dynamicSmemBytes = 0;
        cfg.stream = 0;
        cfg.attrs = attr;
        cfg.numAttrs = 1;
        cudaLaunchKernelEx(&cfg, gather_kernel, cls, coord, mem, out);
    }
}